// round 4
// baseline (speedup 1.0000x reference)
#include <cuda_runtime.h>
#include <math.h>

// Problem constants (fixed by the reference setup)
#define Bd   128
#define Vd   4
#define Dd   128
#define Nd   512           // B*V
#define ANCH 4             // anchors per block
#define GRID (Nd / ANCH)   // 128 blocks
#define NT   512           // threads per block (16 warps)
#define TILE 128           // rows staged per tile
#define NTIL (Nd / TILE)   // 4 tiles
#define RS   132           // padded row stride in floats (conflict-free LDS.128)
#define PRS  21            // partial stride (gcd(21,32)=1, conflict-free)

#define SM_TILES (2 * TILE * RS)       // double-buffered tiles
#define SM_SDM   (ANCH * Nd)           // distance rows
#define SM_SA    (ANCH * Dd)           // anchor rows
#define SM_PRT   (TILE * PRS)          // quarter partials
#define DYN_SMEM_BYTES ((SM_TILES + SM_SDM + SM_SA + SM_PRT) * 4)

// Scratch (device globals — no allocation allowed)
__device__ float        g_part[GRID];
__device__ unsigned int g_cntp[GRID];
__device__ unsigned int g_done = 0;

// ---- packed fp32x2 helpers ----
__device__ __forceinline__ void fma2(unsigned long long& acc,
                                     unsigned long long a,
                                     unsigned long long b) {
    asm("fma.rn.f32x2 %0, %1, %2, %0;" : "+l"(acc) : "l"(a), "l"(b));
}
__device__ __forceinline__ float sum2(unsigned long long v) {
    float lo, hi;
    asm("mov.b64 {%0,%1}, %2;" : "=f"(lo), "=f"(hi) : "l"(v));
    return lo + hi;
}

// ---- cp.async helpers ----
__device__ __forceinline__ void cp16(unsigned dst, const void* src) {
    asm volatile("cp.async.cg.shared.global [%0], [%1], 16;" :: "r"(dst), "l"(src));
}
#define CP_COMMIT() asm volatile("cp.async.commit_group;")
#define CP_WAIT1()  asm volatile("cp.async.wait_group 1;")
#define CP_WAIT0()  asm volatile("cp.async.wait_group 0;")

__global__ void __launch_bounds__(NT, 1)
fused_triplet_kernel(const float* __restrict__ feat,
                     const int*   __restrict__ labels,
                     float*       __restrict__ out) {
    extern __shared__ float smem[];
    float* tiles = smem;                   // 2 * TILE * RS
    float* sdm   = tiles + SM_TILES;       // ANCH * Nd
    float* sa    = sdm + SM_SDM;           // ANCH * Dd
    float* prt   = sa + SM_SA;             // TILE * PRS

    __shared__ int          slab[Nd];
    __shared__ int          spos[Nd];
    __shared__ float        spp[Nd];
    __shared__ int          snpos;
    __shared__ float        s_invna[ANCH];
    __shared__ float        swsum[16];
    __shared__ unsigned int swcnt[16];
    __shared__ int          sIsLast;

    const int t    = threadIdx.x;
    const int w    = t >> 5;
    const int lane = t & 31;
    const int blk  = blockIdx.x;

    // row n of emb <- features[n & 127, n >> 7, :]
    auto row_ptr = [&](int n) -> const float* {
        return feat + (size_t)(n & (Bd - 1)) * (Vd * Dd) + (n >> 7) * Dd;
    };

    // ---- prefetch tiles 0 and 1 (warp w stages rows w*8 .. w*8+7) ----
    {
        unsigned base0 = (unsigned)__cvta_generic_to_shared(tiles);
        unsigned base1 = (unsigned)__cvta_generic_to_shared(tiles + TILE * RS);
#pragma unroll
        for (int rr = 0; rr < 8; rr++) {
            int lrow = w * 8 + rr;
            cp16(base0 + (lrow * RS) * 4 + lane * 16, row_ptr(lrow) + lane * 4);
        }
        CP_COMMIT();
#pragma unroll
        for (int rr = 0; rr < 8; rr++) {
            int lrow = w * 8 + rr;
            cp16(base1 + (lrow * RS) * 4 + lane * 16, row_ptr(TILE + lrow) + lane * 4);
        }
        CP_COMMIT();
    }

    // ---- labels + anchor rows (overlap with cp.async) ----
    slab[t] = labels[t & (Bd - 1)];
    {
        int i = t >> 7;          // 0..3
        int d = t & (Dd - 1);    // 0..127
        int n = blk * ANCH + i;
        sa[i * Dd + d] = row_ptr(n)[d];
    }
    __syncthreads();

    // anchor inverse norms (warps 0..3)
    if (w < ANCH) {
        float4 v = reinterpret_cast<const float4*>(sa + w * Dd)[lane];
        float s = v.x * v.x + v.y * v.y + v.z * v.z + v.w * v.w;
#pragma unroll
        for (int o = 16; o > 0; o >>= 1) s += __shfl_xor_sync(0xffffffffu, s, o);
        if (lane == 0) s_invna[w] = 1.0f / sqrtf(s);
    }
    // published by the __syncthreads() after the first CP_WAIT below

    const int r  = t & (TILE - 1);   // row within tile
    const int kq = t >> 7;           // k-quarter: 0..3

    const ulonglong2* a0p = reinterpret_cast<const ulonglong2*>(sa + 0 * Dd + kq * 32);
    const ulonglong2* a1p = reinterpret_cast<const ulonglong2*>(sa + 1 * Dd + kq * 32);
    const ulonglong2* a2p = reinterpret_cast<const ulonglong2*>(sa + 2 * Dd + kq * 32);
    const ulonglong2* a3p = reinterpret_cast<const ulonglong2*>(sa + 3 * Dd + kq * 32);

#pragma unroll
    for (int tt = 0; tt < NTIL; tt++) {
        if (tt < NTIL - 1) { CP_WAIT1(); } else { CP_WAIT0(); }
        __syncthreads();   // tile tt visible to all; also publishes s_invna on tt==0

        const float* buf = tiles + (tt & 1) * TILE * RS;
        const ulonglong2* rowp =
            reinterpret_cast<const ulonglong2*>(buf + r * RS + kq * 32);

        unsigned long long acc[5][2] = {{0ull,0ull},{0ull,0ull},{0ull,0ull},
                                        {0ull,0ull},{0ull,0ull}};
#pragma unroll
        for (int c = 0; c < 8; c++) {
            ulonglong2 f  = rowp[c];
            ulonglong2 a0 = a0p[c];
            ulonglong2 a1 = a1p[c];
            ulonglong2 a2 = a2p[c];
            ulonglong2 a3 = a3p[c];
            fma2(acc[0][0], f.x, a0.x);  fma2(acc[0][1], f.y, a0.y);
            fma2(acc[1][0], f.x, a1.x);  fma2(acc[1][1], f.y, a1.y);
            fma2(acc[2][0], f.x, a2.x);  fma2(acc[2][1], f.y, a2.y);
            fma2(acc[3][0], f.x, a3.x);  fma2(acc[3][1], f.y, a3.y);
            fma2(acc[4][0], f.x, f.x);   fma2(acc[4][1], f.y, f.y);
        }
        float q0 = sum2(acc[0][0]) + sum2(acc[0][1]);
        float q1 = sum2(acc[1][0]) + sum2(acc[1][1]);
        float q2 = sum2(acc[2][0]) + sum2(acc[2][1]);
        float q3 = sum2(acc[3][0]) + sum2(acc[3][1]);
        float qs = sum2(acc[4][0]) + sum2(acc[4][1]);

        if (kq != 0) {
            float* pp = prt + r * PRS + kq * 5;
            pp[0] = q0; pp[1] = q1; pp[2] = q2; pp[3] = q3; pp[4] = qs;
        }
        __syncthreads();
        if (kq == 0) {
            const float* pp = prt + r * PRS;
#pragma unroll
            for (int k = 1; k < 4; k++) {
                q0 += pp[k * 5 + 0]; q1 += pp[k * 5 + 1];
                q2 += pp[k * 5 + 2]; q3 += pp[k * 5 + 3];
                qs += pp[k * 5 + 4];
            }
            float invnj = 1.0f / sqrtf(qs);
            int gj = tt * TILE + r;
            float c0 = q0 * s_invna[0] * invnj;
            float c1 = q1 * s_invna[1] * invnj;
            float c2 = q2 * s_invna[2] * invnj;
            float c3 = q3 * s_invna[3] * invnj;
            sdm[0 * Nd + gj] = sqrtf(fmaxf(2.f - 2.f * c0, 0.f));
            sdm[1 * Nd + gj] = sqrtf(fmaxf(2.f - 2.f * c1, 0.f));
            sdm[2 * Nd + gj] = sqrtf(fmaxf(2.f - 2.f * c2, 0.f));
            sdm[3 * Nd + gj] = sqrtf(fmaxf(2.f - 2.f * c3, 0.f));
        }
        __syncthreads();   // compute done before buffer is overwritten

        // prefetch tile tt+2 into the buffer tile tt just vacated
        if (tt + 2 < NTIL) {
            unsigned dst = (unsigned)__cvta_generic_to_shared(
                tiles + (tt & 1) * TILE * RS);
#pragma unroll
            for (int rr = 0; rr < 8; rr++) {
                int lrow = w * 8 + rr;
                cp16(dst + (lrow * RS) * 4 + lane * 16,
                     row_ptr((tt + 2) * TILE + lrow) + lane * 4);
            }
            CP_COMMIT();
        }
    }

    // ---- triplet reduction: thread t = candidate negative n ----
    float        lsum = 0.0f;
    unsigned int lcnt = 0;

#pragma unroll
    for (int i = 0; i < ANCH; i++) {
        int a  = blk * ANCH + i;
        int la = slab[a];

        if (t == 0) snpos = 0;
        __syncthreads();
        if (slab[t] == la && t != a) {
            int k = atomicAdd(&snpos, 1);
            spos[k] = t;
        }
        __syncthreads();
        int P = snpos;
        if (t < P) spp[t] = sdm[i * Nd + spos[t]];   // pre-gather positive distances
        __syncthreads();

        if (slab[t] != la) {
            float dan = sdm[i * Nd + t];
#pragma unroll 4
            for (int q = 0; q < P; q++) {
                float diff = spp[q] - dan;   // margin = 0
                if (diff > 0.0f) { lsum += diff; lcnt++; }
            }
        }
        __syncthreads();   // spos/spp reused next anchor
    }

    // ---- block reduce (sum, count) ----
#pragma unroll
    for (int o = 16; o > 0; o >>= 1) {
        lsum += __shfl_xor_sync(0xffffffffu, lsum, o);
        lcnt += __shfl_xor_sync(0xffffffffu, lcnt, o);
    }
    if (lane == 0) { swsum[w] = lsum; swcnt[w] = lcnt; }
    __syncthreads();

    if (t == 0) {
        float bs = 0.0f; unsigned int bc = 0;
#pragma unroll
        for (int k = 0; k < 16; k++) { bs += swsum[k]; bc += swcnt[k]; }
        g_part[blk] = bs;
        g_cntp[blk] = bc;
        __threadfence();
        unsigned int old = atomicAdd(&g_done, 1);
        sIsLast = (old == GRID - 1);
    }
    __syncthreads();

    // ---- last block finalizes (AvgNonZeroReducer) ----
    if (sIsLast) {
        __threadfence();
        float        s = 0.0f;
        unsigned int c = 0;
        if (t < GRID) {
            s = ((volatile float*)g_part)[t];
            c = ((volatile unsigned int*)g_cntp)[t];
        }
#pragma unroll
        for (int o = 16; o > 0; o >>= 1) {
            s += __shfl_xor_sync(0xffffffffu, s, o);
            c += __shfl_xor_sync(0xffffffffu, c, o);
        }
        if (t < GRID && lane == 0) { swsum[w] = s; swcnt[w] = c; }
        __syncthreads();
        if (t == 0) {
            float S = swsum[0] + swsum[1] + swsum[2] + swsum[3];
            unsigned int C = swcnt[0] + swcnt[1] + swcnt[2] + swcnt[3];
            out[0] = (C > 0) ? (S / (float)C) : 0.0f;
            g_done = 0;   // reset for next graph replay
        }
    }
}

extern "C" void kernel_launch(void* const* d_in, const int* in_sizes, int n_in,
                              void* d_out, int out_size) {
    const float* feat   = (const float*)d_in[0];   // [128, 4, 128] float32
    const int*   labels = (const int*)d_in[1];     // [128] int32
    float*       out    = (float*)d_out;           // scalar float32

    cudaFuncSetAttribute(fused_triplet_kernel,
                         cudaFuncAttributeMaxDynamicSharedMemorySize,
                         DYN_SMEM_BYTES);
    fused_triplet_kernel<<<GRID, NT, DYN_SMEM_BYTES>>>(feat, labels, out);
}

// round 5
// speedup vs baseline: 1.1045x; 1.1045x over previous
#include <cuda_runtime.h>
#include <math.h>

// Problem constants (fixed by the reference setup)
#define Bd   128
#define Vd   4
#define Dd   128
#define Nd   512           // B*V
#define ANCH 4             // anchors per block
#define GRID (Nd / ANCH)   // 128 blocks
#define NT   512           // threads per block (16 warps)
#define TILE 256           // rows staged per tile
#define NTIL (Nd / TILE)   // 2 tiles
#define RS   132           // padded row stride in floats (conflict-free LDS.128)
#define PRS  5             // partial stride (gcd(5,32)=1, conflict-free)

#define SM_TILE (TILE * RS)            // single-buffered tile (135 KB)
#define SM_SDM  (ANCH * Nd)            // distance rows
#define SM_SA   (ANCH * Dd)            // anchor rows
#define SM_PRT  (TILE * PRS)           // k-half partials
#define DYN_SMEM_BYTES ((SM_TILE + SM_SDM + SM_SA + SM_PRT) * 4)

// Scratch (device globals — no allocation allowed)
__device__ float        g_part[GRID];
__device__ unsigned int g_cntp[GRID];
__device__ unsigned int g_done = 0;

__global__ void __launch_bounds__(NT, 1)
fused_triplet_kernel(const float* __restrict__ feat,
                     const int*   __restrict__ labels,
                     float*       __restrict__ out) {
    extern __shared__ float smem[];
    float* tile = smem;                 // TILE * RS
    float* sdm  = tile + SM_TILE;       // ANCH * Nd
    float* sa   = sdm + SM_SDM;         // ANCH * Dd
    float* prt  = sa + SM_SA;           // TILE * PRS

    __shared__ int          slab[Nd];
    __shared__ int          spos[ANCH][Nd / 2];   // positive indices per anchor
    __shared__ float        spp[ANCH][Nd / 2];    // positive distances per anchor
    __shared__ int          snpos[ANCH];
    __shared__ float        s_invna[ANCH];
    __shared__ float        swsum[16];
    __shared__ unsigned int swcnt[16];
    __shared__ int          sIsLast;

    const int t    = threadIdx.x;
    const int w    = t >> 5;
    const int lane = t & 31;
    const int blk  = blockIdx.x;

    // row n of emb <- features[n & 127, n >> 7, :]
    auto row_ptr = [&](int n) -> const float* {
        return feat + (size_t)(n & (Bd - 1)) * (Vd * Dd) + (n >> 7) * Dd;
    };

    // ---- stage tile 0: warp w stages rows w*16 .. w*16+15 (coalesced) ----
#pragma unroll
    for (int rr = 0; rr < 16; rr++) {
        int lrow = w * 16 + rr;
        reinterpret_cast<float4*>(tile + lrow * RS)[lane] =
            reinterpret_cast<const float4*>(row_ptr(lrow))[lane];
    }

    // labels + anchor rows (overlaps with the staging loads above)
    slab[t] = labels[t & (Bd - 1)];
    if (t < ANCH * Dd) {
        int i = t >> 7;
        int d = t & (Dd - 1);
        int n = blk * ANCH + i;
        sa[i * Dd + d] = row_ptr(n)[d];
    }
    if (t < ANCH) snpos[t] = 0;
    __syncthreads();

    // anchor inverse norms (warps 0..3; published by the next sync)
    if (w < ANCH) {
        float4 v = reinterpret_cast<const float4*>(sa + w * Dd)[lane];
        float s = v.x * v.x + v.y * v.y + v.z * v.z + v.w * v.w;
#pragma unroll
        for (int o = 16; o > 0; o >>= 1) s += __shfl_xor_sync(0xffffffffu, s, o);
        if (lane == 0) s_invna[w] = 1.0f / sqrtf(s);
    }

    const int r  = t & (TILE - 1);   // row within tile (lanes of a warp = consecutive r)
    const int kh = t >> 8;           // k-half: 0 or 1

    const float4* a0p = reinterpret_cast<const float4*>(sa + 0 * Dd + kh * 64);
    const float4* a1p = reinterpret_cast<const float4*>(sa + 1 * Dd + kh * 64);
    const float4* a2p = reinterpret_cast<const float4*>(sa + 2 * Dd + kh * 64);
    const float4* a3p = reinterpret_cast<const float4*>(sa + 3 * Dd + kh * 64);

#pragma unroll
    for (int tt = 0; tt < NTIL; tt++) {
        // ---- compute: thread owns (row r, k-half kh); anchors via broadcast LDS ----
        const float4* rowp = reinterpret_cast<const float4*>(tile + r * RS + kh * 64);
        float d0 = 0.f, d1 = 0.f, d2 = 0.f, d3 = 0.f, sq = 0.f;
#pragma unroll
        for (int c = 0; c < 16; c++) {
            float4 f  = rowp[c];    // conflict-free: RS=132 -> banks 4r mod 32 distinct
            float4 a0 = a0p[c];     // warp-uniform address -> broadcast (1 phase)
            float4 a1 = a1p[c];
            float4 a2 = a2p[c];
            float4 a3 = a3p[c];
            sq += f.x * f.x  + f.y * f.y  + f.z * f.z  + f.w * f.w;
            d0 += f.x * a0.x + f.y * a0.y + f.z * a0.z + f.w * a0.w;
            d1 += f.x * a1.x + f.y * a1.y + f.z * a1.z + f.w * a1.w;
            d2 += f.x * a2.x + f.y * a2.y + f.z * a2.z + f.w * a2.w;
            d3 += f.x * a3.x + f.y * a3.y + f.z * a3.z + f.w * a3.w;
        }
        if (kh == 1) {
            float* pp = prt + r * PRS;
            pp[0] = d0; pp[1] = d1; pp[2] = d2; pp[3] = d3; pp[4] = sq;
        }
        __syncthreads();
        if (kh == 0) {
            const float* pp = prt + r * PRS;
            d0 += pp[0]; d1 += pp[1]; d2 += pp[2]; d3 += pp[3]; sq += pp[4];
            float invnj = 1.0f / sqrtf(sq);
            int gj = tt * TILE + r;
            float c0 = d0 * s_invna[0] * invnj;
            float c1 = d1 * s_invna[1] * invnj;
            float c2 = d2 * s_invna[2] * invnj;
            float c3 = d3 * s_invna[3] * invnj;
            sdm[0 * Nd + gj] = sqrtf(fmaxf(2.f - 2.f * c0, 0.f));
            sdm[1 * Nd + gj] = sqrtf(fmaxf(2.f - 2.f * c1, 0.f));
            sdm[2 * Nd + gj] = sqrtf(fmaxf(2.f - 2.f * c2, 0.f));
            sdm[3 * Nd + gj] = sqrtf(fmaxf(2.f - 2.f * c3, 0.f));
        }
        // stage the next tile (tile buffer fully consumed by the compute above)
        if (tt + 1 < NTIL) {
#pragma unroll
            for (int rr = 0; rr < 16; rr++) {
                int lrow = w * 16 + rr;
                reinterpret_cast<float4*>(tile + lrow * RS)[lane] =
                    reinterpret_cast<const float4*>(row_ptr((tt + 1) * TILE + lrow))[lane];
            }
        }
        __syncthreads();   // stage complete + prt safe for reuse
    }

    // ---- gather positive lists for all 4 anchors in one pass ----
    {
        int myl = slab[t];
#pragma unroll
        for (int i = 0; i < ANCH; i++) {
            int a = blk * ANCH + i;
            if (myl == slab[a] && t != a) {
                int k = atomicAdd(&snpos[i], 1);
                spos[i][k] = t;
            }
        }
    }
    __syncthreads();
    {
#pragma unroll
        for (int i = 0; i < ANCH; i++) {
            if (t < snpos[i]) spp[i][t] = sdm[i * Nd + spos[i][t]];
        }
    }
    __syncthreads();

    // ---- triplet reduction: thread t = candidate negative n ----
    float        lsum = 0.0f;
    unsigned int lcnt = 0;
    {
        int myl = slab[t];
#pragma unroll
        for (int i = 0; i < ANCH; i++) {
            int a = blk * ANCH + i;
            if (myl != slab[a]) {
                float dan = sdm[i * Nd + t];
                int P = snpos[i];
#pragma unroll 4
                for (int q = 0; q < P; q++) {
                    float diff = spp[i][q] - dan;   // margin = 0
                    if (diff > 0.0f) { lsum += diff; lcnt++; }
                }
            }
        }
    }

    // ---- block reduce (sum, count) ----
#pragma unroll
    for (int o = 16; o > 0; o >>= 1) {
        lsum += __shfl_xor_sync(0xffffffffu, lsum, o);
        lcnt += __shfl_xor_sync(0xffffffffu, lcnt, o);
    }
    if (lane == 0) { swsum[w] = lsum; swcnt[w] = lcnt; }
    __syncthreads();

    if (t == 0) {
        float bs = 0.0f; unsigned int bc = 0;
#pragma unroll
        for (int k = 0; k < 16; k++) { bs += swsum[k]; bc += swcnt[k]; }
        g_part[blk] = bs;
        g_cntp[blk] = bc;
        __threadfence();
        unsigned int old = atomicAdd(&g_done, 1);
        sIsLast = (old == GRID - 1);
    }
    __syncthreads();

    // ---- last block finalizes (AvgNonZeroReducer) ----
    if (sIsLast) {
        __threadfence();
        float        s = 0.0f;
        unsigned int c = 0;
        if (t < GRID) {
            s = ((volatile float*)g_part)[t];
            c = ((volatile unsigned int*)g_cntp)[t];
        }
#pragma unroll
        for (int o = 16; o > 0; o >>= 1) {
            s += __shfl_xor_sync(0xffffffffu, s, o);
            c += __shfl_xor_sync(0xffffffffu, c, o);
        }
        if (t < GRID && lane == 0) { swsum[w] = s; swcnt[w] = c; }
        __syncthreads();
        if (t == 0) {
            float S = swsum[0] + swsum[1] + swsum[2] + swsum[3];
            unsigned int C = swcnt[0] + swcnt[1] + swcnt[2] + swcnt[3];
            out[0] = (C > 0) ? (S / (float)C) : 0.0f;
            g_done = 0;   // reset for next graph replay
        }
    }
}

extern "C" void kernel_launch(void* const* d_in, const int* in_sizes, int n_in,
                              void* d_out, int out_size) {
    const float* feat   = (const float*)d_in[0];   // [128, 4, 128] float32
    const int*   labels = (const int*)d_in[1];     // [128] int32
    float*       out    = (float*)d_out;           // scalar float32

    cudaFuncSetAttribute(fused_triplet_kernel,
                         cudaFuncAttributeMaxDynamicSharedMemorySize,
                         DYN_SMEM_BYTES);
    fused_triplet_kernel<<<GRID, NT, DYN_SMEM_BYTES>>>(feat, labels, out);
}